// round 1
// baseline (speedup 1.0000x reference)
#include <cuda_runtime.h>
#include <math.h>

#define Bb   2
#define Ss   4096
#define Hh   512
#define NHh  8
#define HDd  64
#define QKV3 1536

// Scratch (allocation-free rule: __device__ globals)
__device__ float g_qkv[(size_t)Bb * Ss * QKV3];   // [B,S,3*H]
__device__ float g_att[(size_t)Bb * Ss * Hh];     // [B,S,H] attention output

// ---------------------------------------------------------------------------
// C[M,N] = A[M,K] @ B[N,K]^T (+ bias[N] if bias != nullptr)
// 64x64 block tile, BK=16, 256 threads, 4x4 micro-tile per thread.
// ---------------------------------------------------------------------------
__global__ __launch_bounds__(256) void gemm_abt(
    const float* __restrict__ A, const float* __restrict__ Bm,
    const float* __restrict__ bias, float* __restrict__ C,
    int M, int N, int K)
{
    __shared__ float As[64][17];
    __shared__ float Bs[64][17];

    const int tid = threadIdx.x;
    const int tx  = tid & 15;        // 0..15  -> 4 output cols each
    const int ty  = tid >> 4;        // 0..15  -> 4 output rows each
    const int tx4 = tx * 4, ty4 = ty * 4;
    const int m0 = blockIdx.y * 64, n0 = blockIdx.x * 64;
    const int lr = tid >> 2;          // load row 0..63
    const int lc = (tid & 3) * 4;     // load col {0,4,8,12}

    float acc[4][4] = {};

    for (int k0 = 0; k0 < K; k0 += 16) {
        float4 av = *(const float4*)&A [(size_t)(m0 + lr) * K + k0 + lc];
        float4 bv = *(const float4*)&Bm[(size_t)(n0 + lr) * K + k0 + lc];
        As[lr][lc + 0] = av.x; As[lr][lc + 1] = av.y;
        As[lr][lc + 2] = av.z; As[lr][lc + 3] = av.w;
        Bs[lr][lc + 0] = bv.x; Bs[lr][lc + 1] = bv.y;
        Bs[lr][lc + 2] = bv.z; Bs[lr][lc + 3] = bv.w;
        __syncthreads();

        #pragma unroll
        for (int k = 0; k < 16; k++) {
            float a[4], b[4];
            #pragma unroll
            for (int r = 0; r < 4; r++) a[r] = As[ty4 + r][k];
            #pragma unroll
            for (int c = 0; c < 4; c++) b[c] = Bs[tx4 + c][k];
            #pragma unroll
            for (int r = 0; r < 4; r++)
                #pragma unroll
                for (int c = 0; c < 4; c++)
                    acc[r][c] += a[r] * b[c];
        }
        __syncthreads();
    }

    #pragma unroll
    for (int r = 0; r < 4; r++) {
        float4 o = make_float4(acc[r][0], acc[r][1], acc[r][2], acc[r][3]);
        if (bias) {
            o.x += bias[n0 + tx4 + 0];
            o.y += bias[n0 + tx4 + 1];
            o.z += bias[n0 + tx4 + 2];
            o.w += bias[n0 + tx4 + 3];
        }
        *(float4*)&C[(size_t)(m0 + ty4 + r) * N + n0 + tx4] = o;
    }
}

// ---------------------------------------------------------------------------
// Fused flash attention with recency bias (NON-causal: bias only for j<=i).
// Grid: (S/64, NH, B). Block: 256 threads. Each block: 64 queries x 1 head.
// Online softmax over 64 KV tiles of 64 keys each.
// smem: Qs[64][65], Ks[64][65], Vs[64][64], Ps[64][68]  = 67072 B (dynamic)
// ---------------------------------------------------------------------------
__global__ __launch_bounds__(256) void attn_kernel()
{
    extern __shared__ float sm[];
    float* Qs = sm;                        // [64][65]
    float* Ks = sm + 64 * 65;              // [64][65]
    float* Vs = sm + 2 * 64 * 65;          // [64][64]
    float* Ps = sm + 2 * 64 * 65 + 64 * 64;// [64][68]

    const int tid = threadIdx.x;
    const int tx  = tid & 15;
    const int ty  = tid >> 4;
    const int tx4 = tx * 4, ty4 = ty * 4;
    const int qbase = blockIdx.x * 64;
    const int h = blockIdx.y;
    const int b = blockIdx.z;

    const float* qg = g_qkv + (size_t)b * Ss * QKV3 + h * HDd;       // q
    const float* kg = qg + 512;                                      // k
    const float* vg = qg + 1024;                                     // v

    // Load Q tile (64 rows x 64 dims)
    #pragma unroll
    for (int i = 0; i < 4; i++) {
        int e4  = tid + i * 256;          // float4 index 0..1023
        int row = e4 >> 4;
        int d4  = (e4 & 15) << 2;
        float4 v = *(const float4*)&qg[(size_t)(qbase + row) * QKV3 + d4];
        float* q = &Qs[row * 65 + d4];
        q[0] = v.x; q[1] = v.y; q[2] = v.z; q[3] = v.w;
    }

    float m[4]      = {-1e30f, -1e30f, -1e30f, -1e30f};
    float l[4]      = {0.f, 0.f, 0.f, 0.f};
    float acc[4][4] = {};
    const float LOGD = -0.10536051565782628f;   // log(0.9)

    __syncthreads();

    for (int kb = 0; kb < Ss; kb += 64) {
        // Load K & V tiles
        #pragma unroll
        for (int i = 0; i < 4; i++) {
            int e4  = tid + i * 256;
            int row = e4 >> 4;
            int d4  = (e4 & 15) << 2;
            float4 kv = *(const float4*)&kg[(size_t)(kb + row) * QKV3 + d4];
            float* kp = &Ks[row * 65 + d4];
            kp[0] = kv.x; kp[1] = kv.y; kp[2] = kv.z; kp[3] = kv.w;
            float4 vv = *(const float4*)&vg[(size_t)(kb + row) * QKV3 + d4];
            *(float4*)&Vs[row * 64 + d4] = vv;
        }
        __syncthreads();

        // S = Q K^T   (4x4 scores per thread)
        float s[4][4] = {};
        #pragma unroll 8
        for (int d = 0; d < 64; d++) {
            float a[4], bk[4];
            #pragma unroll
            for (int r = 0; r < 4; r++) a[r]  = Qs[(ty4 + r) * 65 + d];
            #pragma unroll
            for (int c = 0; c < 4; c++) bk[c] = Ks[(tx4 + c) * 65 + d];
            #pragma unroll
            for (int r = 0; r < 4; r++)
                #pragma unroll
                for (int c = 0; c < 4; c++)
                    s[r][c] += a[r] * bk[c];
        }

        // scale + recency bias + online softmax (row groups = 16 lanes)
        #pragma unroll
        for (int rr = 0; rr < 4; rr++) {
            const int iq = qbase + ty4 + rr;
            float rmax = -1e30f;
            #pragma unroll
            for (int cc = 0; cc < 4; cc++) {
                int j   = kb + tx4 + cc;
                float t = s[rr][cc] * 0.125f
                        + fmaxf((float)(j - iq) * LOGD, 0.0f);
                s[rr][cc] = t;
                rmax = fmaxf(rmax, t);
            }
            rmax = fmaxf(rmax, __shfl_xor_sync(0xffffffffu, rmax, 1));
            rmax = fmaxf(rmax, __shfl_xor_sync(0xffffffffu, rmax, 2));
            rmax = fmaxf(rmax, __shfl_xor_sync(0xffffffffu, rmax, 4));
            rmax = fmaxf(rmax, __shfl_xor_sync(0xffffffffu, rmax, 8));

            float mn   = fmaxf(m[rr], rmax);
            float corr = __expf(m[rr] - mn);
            m[rr] = mn;

            float rs = 0.f;
            #pragma unroll
            for (int cc = 0; cc < 4; cc++) {
                float p = __expf(s[rr][cc] - mn);
                s[rr][cc] = p;
                rs += p;
            }
            rs += __shfl_xor_sync(0xffffffffu, rs, 1);
            rs += __shfl_xor_sync(0xffffffffu, rs, 2);
            rs += __shfl_xor_sync(0xffffffffu, rs, 4);
            rs += __shfl_xor_sync(0xffffffffu, rs, 8);

            l[rr] = l[rr] * corr + rs;
            #pragma unroll
            for (int cc = 0; cc < 4; cc++) acc[rr][cc] *= corr;

            *(float4*)&Ps[(ty4 + rr) * 68 + tx4] =
                make_float4(s[rr][0], s[rr][1], s[rr][2], s[rr][3]);
        }
        __syncthreads();

        // O += P V   (each thread: 4 rows x 4 output dims tx4..tx4+3)
        #pragma unroll 8
        for (int j = 0; j < 64; j++) {
            float p[4];
            #pragma unroll
            for (int r = 0; r < 4; r++) p[r] = Ps[(ty4 + r) * 68 + j];
            float4 v = *(const float4*)&Vs[j * 64 + tx4];
            #pragma unroll
            for (int r = 0; r < 4; r++) {
                acc[r][0] += p[r] * v.x;
                acc[r][1] += p[r] * v.y;
                acc[r][2] += p[r] * v.z;
                acc[r][3] += p[r] * v.w;
            }
        }
        __syncthreads();
    }

    // epilogue: normalize and write [B,S,H] with head-contiguous layout
    #pragma unroll
    for (int rr = 0; rr < 4; rr++) {
        float inv = 1.0f / l[rr];
        float4 o = make_float4(acc[rr][0] * inv, acc[rr][1] * inv,
                               acc[rr][2] * inv, acc[rr][3] * inv);
        *(float4*)&g_att[((size_t)(b * Ss + qbase + ty4 + rr)) * Hh
                         + h * HDd + tx4] = o;
    }
}

// ---------------------------------------------------------------------------

static const int ATTN_SMEM = (2 * 64 * 65 + 64 * 64 + 64 * 68) * 4;  // 67072

extern "C" void kernel_launch(void* const* d_in, const int* in_sizes, int n_in,
                              void* d_out, int out_size)
{
    const float* x     = (const float*)d_in[0];
    const float* w_qkv = (const float*)d_in[1];
    const float* w_out = (const float*)d_in[2];
    const float* b_out = (const float*)d_in[3];
    float* out = (float*)d_out;

    float* qkv = nullptr;
    float* att = nullptr;
    cudaGetSymbolAddress((void**)&qkv, g_qkv);
    cudaGetSymbolAddress((void**)&att, g_att);

    cudaFuncSetAttribute(attn_kernel,
                         cudaFuncAttributeMaxDynamicSharedMemorySize, ATTN_SMEM);

    // 1) qkv = x @ w_qkv^T           [8192,512] x [1536,512]^T
    gemm_abt<<<dim3(QKV3 / 64, (Bb * Ss) / 64), 256>>>(
        x, w_qkv, nullptr, qkv, Bb * Ss, QKV3, Hh);

    // 2) fused recency-biased attention
    attn_kernel<<<dim3(Ss / 64, NHh, Bb), 256, ATTN_SMEM>>>();

    // 3) out = att @ w_out^T + b_out [8192,512] x [512,512]^T
    gemm_abt<<<dim3(Hh / 64, (Bb * Ss) / 64), 256>>>(
        att, w_out, b_out, out, Bb * Ss, Hh, Hh);
}